// round 2
// baseline (speedup 1.0000x reference)
#include <cuda_runtime.h>

// Problem constants (fixed by the reference setup_inputs)
#define PB 4
#define PC 3
#define PH 512
#define PW 512
#define PS 16
#define HW (PH * PW)          // 262144 = 1<<18

// Scratch: channel-interleaved image, (B,H,W) of float4 {c0,c1,c2,0}. 16 MB.
__device__ float4 g_pack[PB * HW];

// ---------------------------------------------------------------------------
// Pass 1: planar (B,C,H,W) -> interleaved float4 (B,H,W,4)
// ---------------------------------------------------------------------------
__global__ __launch_bounds__(256) void pack_kernel(const float* __restrict__ img) {
    int idx = blockIdx.x * blockDim.x + threadIdx.x;   // over B*H*W
    if (idx >= PB * HW) return;
    int b = idx >> 18;
    int p = idx & (HW - 1);
    const float* base = img + (size_t)b * PC * HW + p;
    float c0 = __ldg(base);
    float c1 = __ldg(base + HW);
    float c2 = __ldg(base + 2 * HW);
    g_pack[idx] = make_float4(c0, c1, c2, 0.0f);
}

// ---------------------------------------------------------------------------
// Pass 2: 16-step motion blur, bilinear border-clamped sampling.
// One thread per (b, y, x); all 3 channels via float4 gathers.
// ---------------------------------------------------------------------------
__global__ __launch_bounds__(256) void blur_kernel(const float* __restrict__ dx,
                                                   float* __restrict__ out) {
    int idx = blockIdx.x * blockDim.x + threadIdx.x;   // over B*H*W
    if (idx >= PB * HW) return;
    int b = idx >> 18;
    int p = idx & (HW - 1);
    int y = p >> 9;
    int x = p & (PW - 1);

    const float dxx = __ldg(dx + (size_t)(b * 2)     * HW + p);
    const float dxy = __ldg(dx + (size_t)(b * 2 + 1) * HW + p);

    const float4* __restrict__ base = g_pack + ((size_t)b << 18);

    const float fx = (float)x;
    const float fy = (float)y;

    float a0 = 0.0f, a1 = 0.0f, a2 = 0.0f;

#pragma unroll
    for (int s = 0; s < PS; s++) {
        // t = (s+0.5)/16 - 0.5  (compile-time constant per unrolled step)
        const float t = ((float)s + 0.5f) * (1.0f / (float)PS) - 0.5f;

        float px = fminf(fmaxf(fmaf(t, dxx, fx), 0.0f), (float)(PW - 1));
        float py = fminf(fmaxf(fmaf(t, dxy, fy), 0.0f), (float)(PH - 1));

        float x0f = floorf(px);
        float y0f = floorf(py);
        float wx = px - x0f;
        float wy = py - y0f;
        int x0 = (int)x0f;
        int y0 = (int)y0f;
        int x1 = min(x0 + 1, PW - 1);
        int y1 = min(y0 + 1, PH - 1);

        int r0 = y0 << 9;
        int r1 = y1 << 9;
        float4 v00 = __ldg(base + r0 + x0);
        float4 v01 = __ldg(base + r0 + x1);
        float4 v10 = __ldg(base + r1 + x0);
        float4 v11 = __ldg(base + r1 + x1);

        float w00 = (1.0f - wx) * (1.0f - wy);
        float w01 = wx * (1.0f - wy);
        float w10 = (1.0f - wx) * wy;
        float w11 = wx * wy;

        a0 = fmaf(v00.x, w00, fmaf(v01.x, w01, fmaf(v10.x, w10, fmaf(v11.x, w11, a0))));
        a1 = fmaf(v00.y, w00, fmaf(v01.y, w01, fmaf(v10.y, w10, fmaf(v11.y, w11, a1))));
        a2 = fmaf(v00.z, w00, fmaf(v01.z, w01, fmaf(v10.z, w10, fmaf(v11.z, w11, a2))));
    }

    const float inv = 1.0f / (float)PS;
    float* o = out + (size_t)b * PC * HW + p;
    o[0]        = a0 * inv;
    o[HW]       = a1 * inv;
    o[2 * HW]   = a2 * inv;
}

extern "C" void kernel_launch(void* const* d_in, const int* in_sizes, int n_in,
                              void* d_out, int out_size) {
    const float* image = (const float*)d_in[0];   // (B,C,H,W) float32
    const float* dx    = (const float*)d_in[1];   // (B,2,H,W) float32
    float* out         = (float*)d_out;           // (B,C,H,W) float32

    const int n = PB * HW;
    const int threads = 256;
    const int blocks = (n + threads - 1) / threads;

    pack_kernel<<<blocks, threads>>>(image);
    blur_kernel<<<blocks, threads>>>(dx, out);
}

// round 3
// speedup vs baseline: 1.0012x; 1.0012x over previous
#include <cuda_runtime.h>

// Problem constants (fixed by the reference setup_inputs)
#define PB 4
#define PC 3
#define PH 512
#define PW 512
#define PS 16
#define HW (PH * PW)          // 262144 = 1<<18

// Scratch: channel-interleaved image, (B,H,W) of float4 {c0,c1,c2,0}. 16 MB.
__device__ float4 g_pack[PB * HW];

// ---------------------------------------------------------------------------
// Pass 1: planar (B,C,H,W) -> interleaved float4 (B,H,W,4)
// ---------------------------------------------------------------------------
__global__ __launch_bounds__(256) void pack_kernel(const float* __restrict__ img) {
    int idx = blockIdx.x * blockDim.x + threadIdx.x;   // over B*H*W
    if (idx >= PB * HW) return;
    int b = idx >> 18;
    int p = idx & (HW - 1);
    const float* base = img + (size_t)b * PC * HW + p;
    float c0 = __ldg(base);
    float c1 = __ldg(base + HW);
    float c2 = __ldg(base + 2 * HW);
    g_pack[idx] = make_float4(c0, c1, c2, 0.0f);
}

// ---------------------------------------------------------------------------
// Pass 2: 16-step motion blur, bilinear border-clamped sampling.
// One thread per (b, y, x); all 3 channels via float4 gathers.
// ---------------------------------------------------------------------------
__global__ __launch_bounds__(256) void blur_kernel(const float* __restrict__ dx,
                                                   float* __restrict__ out) {
    int idx = blockIdx.x * blockDim.x + threadIdx.x;   // over B*H*W
    if (idx >= PB * HW) return;
    int b = idx >> 18;
    int p = idx & (HW - 1);
    int y = p >> 9;
    int x = p & (PW - 1);

    const float dxx = __ldg(dx + (size_t)(b * 2)     * HW + p);
    const float dxy = __ldg(dx + (size_t)(b * 2 + 1) * HW + p);

    const float4* __restrict__ base = g_pack + ((size_t)b << 18);

    const float fx = (float)x;
    const float fy = (float)y;

    float a0 = 0.0f, a1 = 0.0f, a2 = 0.0f;

#pragma unroll
    for (int s = 0; s < PS; s++) {
        // t = (s+0.5)/16 - 0.5  (compile-time constant per unrolled step)
        const float t = ((float)s + 0.5f) * (1.0f / (float)PS) - 0.5f;

        float px = fminf(fmaxf(fmaf(t, dxx, fx), 0.0f), (float)(PW - 1));
        float py = fminf(fmaxf(fmaf(t, dxy, fy), 0.0f), (float)(PH - 1));

        float x0f = floorf(px);
        float y0f = floorf(py);
        float wx = px - x0f;
        float wy = py - y0f;
        int x0 = (int)x0f;
        int y0 = (int)y0f;
        int x1 = min(x0 + 1, PW - 1);
        int y1 = min(y0 + 1, PH - 1);

        int r0 = y0 << 9;
        int r1 = y1 << 9;
        float4 v00 = __ldg(base + r0 + x0);
        float4 v01 = __ldg(base + r0 + x1);
        float4 v10 = __ldg(base + r1 + x0);
        float4 v11 = __ldg(base + r1 + x1);

        float w00 = (1.0f - wx) * (1.0f - wy);
        float w01 = wx * (1.0f - wy);
        float w10 = (1.0f - wx) * wy;
        float w11 = wx * wy;

        a0 = fmaf(v00.x, w00, fmaf(v01.x, w01, fmaf(v10.x, w10, fmaf(v11.x, w11, a0))));
        a1 = fmaf(v00.y, w00, fmaf(v01.y, w01, fmaf(v10.y, w10, fmaf(v11.y, w11, a1))));
        a2 = fmaf(v00.z, w00, fmaf(v01.z, w01, fmaf(v10.z, w10, fmaf(v11.z, w11, a2))));
    }

    const float inv = 1.0f / (float)PS;
    float* o = out + (size_t)b * PC * HW + p;
    o[0]        = a0 * inv;
    o[HW]       = a1 * inv;
    o[2 * HW]   = a2 * inv;
}

extern "C" void kernel_launch(void* const* d_in, const int* in_sizes, int n_in,
                              void* d_out, int out_size) {
    const float* image = (const float*)d_in[0];   // (B,C,H,W) float32
    const float* dx    = (const float*)d_in[1];   // (B,2,H,W) float32
    float* out         = (float*)d_out;           // (B,C,H,W) float32

    const int n = PB * HW;
    const int threads = 256;
    const int blocks = (n + threads - 1) / threads;

    pack_kernel<<<blocks, threads>>>(image);
    blur_kernel<<<blocks, threads>>>(dx, out);
}

// round 4
// speedup vs baseline: 1.3921x; 1.3904x over previous
#include <cuda_runtime.h>

// Problem constants (fixed by the reference setup_inputs)
#define PB 4
#define PC 3
#define PH 512
#define PW 512
#define PS 16
#define HW (PH * PW)          // 262144 = 1<<18

// Scratch: channel-interleaved image, (B,H,W) of float4 {c0,c1,c2,0}. 16 MB.
__device__ float4 g_pack[PB * HW];

// ---------------------------------------------------------------------------
// Pass 1: planar (B,C,H,W) -> interleaved float4 (B,H,W,4)
// ---------------------------------------------------------------------------
__global__ __launch_bounds__(256) void pack_kernel(const float* __restrict__ img) {
    int idx = blockIdx.x * blockDim.x + threadIdx.x;   // over B*H*W
    if (idx >= PB * HW) return;
    int b = idx >> 18;
    int p = idx & (HW - 1);
    const float* base = img + (size_t)b * PC * HW + p;
    float c0 = __ldg(base);
    float c1 = __ldg(base + HW);
    float c2 = __ldg(base + 2 * HW);
    g_pack[idx] = make_float4(c0, c1, c2, 0.0f);
}

// ---------------------------------------------------------------------------
// Pass 2: 16-step motion blur, bilinear border-clamped sampling.
// One thread per (b, y, x). Key optimization: consecutive steps usually land
// in the SAME bilinear cell (step delta = dx/16), so the 4 corner float4s are
// cached in registers and reloaded only when (x0,y0) changes. Masked-off
// lanes generate no L1tex sector traffic, attacking the 88.5% L1 bottleneck.
// ---------------------------------------------------------------------------
__global__ __launch_bounds__(256) void blur_kernel(const float* __restrict__ dx,
                                                   float* __restrict__ out) {
    int idx = blockIdx.x * blockDim.x + threadIdx.x;   // over B*H*W
    if (idx >= PB * HW) return;
    int b = idx >> 18;
    int p = idx & (HW - 1);
    int y = p >> 9;
    int x = p & (PW - 1);

    const float dxx = __ldg(dx + (size_t)(b * 2)     * HW + p);
    const float dxy = __ldg(dx + (size_t)(b * 2 + 1) * HW + p);

    const float4* __restrict__ base = g_pack + ((size_t)b << 18);

    const float fx = (float)x;
    const float fy = (float)y;

    float a0 = 0.0f, a1 = 0.0f, a2 = 0.0f;

    // Register cache of the current bilinear cell's 4 corners.
    int ccell = -1;
    float4 v00 = make_float4(0.f, 0.f, 0.f, 0.f);
    float4 v01 = v00, v10 = v00, v11 = v00;

#pragma unroll
    for (int s = 0; s < PS; s++) {
        // t = (s+0.5)/16 - 0.5  (compile-time constant per unrolled step)
        const float t = ((float)s + 0.5f) * (1.0f / (float)PS) - 0.5f;

        float px = fminf(fmaxf(fmaf(t, dxx, fx), 0.0f), (float)(PW - 1));
        float py = fminf(fmaxf(fmaf(t, dxy, fy), 0.0f), (float)(PH - 1));

        float x0f = floorf(px);
        float y0f = floorf(py);
        float wx = px - x0f;
        float wy = py - y0f;
        int x0 = (int)x0f;
        int y0 = (int)y0f;

        int cell = (y0 << 9) | x0;
        if (cell != ccell) {
            ccell = cell;
            int x1 = min(x0 + 1, PW - 1);
            int y1 = min(y0 + 1, PH - 1);
            int r0 = y0 << 9;
            int r1 = y1 << 9;
            v00 = __ldg(base + r0 + x0);
            v01 = __ldg(base + r0 + x1);
            v10 = __ldg(base + r1 + x0);
            v11 = __ldg(base + r1 + x1);
        }

        float w00 = (1.0f - wx) * (1.0f - wy);
        float w01 = wx * (1.0f - wy);
        float w10 = (1.0f - wx) * wy;
        float w11 = wx * wy;

        a0 = fmaf(v00.x, w00, fmaf(v01.x, w01, fmaf(v10.x, w10, fmaf(v11.x, w11, a0))));
        a1 = fmaf(v00.y, w00, fmaf(v01.y, w01, fmaf(v10.y, w10, fmaf(v11.y, w11, a1))));
        a2 = fmaf(v00.z, w00, fmaf(v01.z, w01, fmaf(v10.z, w10, fmaf(v11.z, w11, a2))));
    }

    const float inv = 1.0f / (float)PS;
    float* o = out + (size_t)b * PC * HW + p;
    o[0]        = a0 * inv;
    o[HW]       = a1 * inv;
    o[2 * HW]   = a2 * inv;
}

extern "C" void kernel_launch(void* const* d_in, const int* in_sizes, int n_in,
                              void* d_out, int out_size) {
    const float* image = (const float*)d_in[0];   // (B,C,H,W) float32
    const float* dx    = (const float*)d_in[1];   // (B,2,H,W) float32
    float* out         = (float*)d_out;           // (B,C,H,W) float32

    const int n = PB * HW;
    const int threads = 256;
    const int blocks = (n + threads - 1) / threads;

    pack_kernel<<<blocks, threads>>>(image);
    blur_kernel<<<blocks, threads>>>(dx, out);
}